// round 3
// baseline (speedup 1.0000x reference)
#include <cuda_runtime.h>
#include <cuda_bf16.h>
#include <math.h>

// Problem constants (shapes are fixed by the dataset)
#define N_NODES 50000
#define N_EDGES 800000
#define E_TOT   (N_EDGES + N_NODES)   // + self loops
#define IN_CH   128
#define HH      96
#define N_GRAPHS 64
#define NEG_SLOPE 0.2f

// ---------------- scratch (no allocations allowed) ----------------
__device__ int   g_flag64[1];            // 1 => indices are int64, 0 => int32
__device__ int   g_src32[N_EDGES];
__device__ int   g_dst32[N_EDGES];
__device__ int   g_batch32[N_NODES];
__device__ int   g_counts[N_NODES];
__device__ int   g_row[N_NODES + 1];
__device__ int   g_cursor[N_NODES];
__device__ int   g_csrsrc[E_TOT];
__device__ float g_h[N_NODES * HH];      // GEMM output (pre-aggregation features)
__device__ float g_bufA[N_NODES * HH];   // layer activations ping
__device__ float g_bufB[N_NODES * HH];   // layer activations pong
__device__ float g_es[N_NODES * 2];
__device__ float g_ed[N_NODES * 2];
__device__ float g_gsum[N_GRAPHS * HH];
__device__ float g_gcnt[N_GRAPHS];

// ---------------- index dtype probe + conversion ----------------
// edge_index values are uniform in [0, 50000). If stored as int64, every odd
// int32 word is 0. If stored as int32, a sampled odd word is nonzero with
// probability ~1 - 2e-5. Check 128 odd words -> effectively zero error rate.
__global__ void probe_kernel(const int* __restrict__ ei32, int* flag) {
    if (threadIdx.x == 0 && blockIdx.x == 0) {
        int odd_nonzero = 0;
        for (int i = 0; i < 128; i++) odd_nonzero += (ei32[2 * i + 1] != 0);
        *flag = (odd_nonzero == 0) ? 1 : 0;
    }
}

__global__ void cvt_kernel(const void* __restrict__ base, long long elem_off,
                           const int* __restrict__ flag, int* __restrict__ out, int n) {
    int i = blockIdx.x * blockDim.x + threadIdx.x;
    if (i >= n) return;
    if (*flag) out[i] = (int)(((const long long*)base)[elem_off + i]);
    else       out[i] = ((const int*)base)[elem_off + i];
}

// ---------------- CSR construction ----------------
__global__ void init_counts_kernel(int* counts, int n) {
    int i = blockIdx.x * blockDim.x + threadIdx.x;
    if (i < n) counts[i] = 1;  // self loop
}

__global__ void hist_kernel(const int* __restrict__ dst, int* counts, int e) {
    int i = blockIdx.x * blockDim.x + threadIdx.x;
    if (i < e) atomicAdd(&counts[dst[i]], 1);
}

// single block, 1024 threads: exclusive scan of counts -> row
__global__ void scan_kernel(const int* __restrict__ counts, int* __restrict__ row, int n) {
    __shared__ int part[1024];
    int t = threadIdx.x;
    int C = (n + 1023) / 1024;
    int lo = t * C, hi = min(lo + C, n);
    int s = 0;
    for (int i = lo; i < hi; i++) s += counts[i];
    part[t] = s;
    __syncthreads();
    for (int off = 1; off < 1024; off <<= 1) {
        int v = (t >= off) ? part[t - off] : 0;
        __syncthreads();
        part[t] += v;
        __syncthreads();
    }
    int base = (t == 0) ? 0 : part[t - 1];
    for (int i = lo; i < hi; i++) { row[i] = base; base += counts[i]; }
    if (t == 1023) row[n] = part[1023];
}

__global__ void selfloop_kernel(const int* __restrict__ row, int* __restrict__ cursor,
                                int* __restrict__ csrsrc, int n) {
    int i = blockIdx.x * blockDim.x + threadIdx.x;
    if (i < n) {
        int r = row[i];
        csrsrc[r] = i;          // self loop first
        cursor[i] = r + 1;
    }
}

__global__ void scatter_kernel(const int* __restrict__ src, const int* __restrict__ dst,
                               int* __restrict__ cursor, int* __restrict__ csrsrc, int e) {
    int i = blockIdx.x * blockDim.x + threadIdx.x;
    if (i < e) {
        int d = dst[i];
        int pos = atomicAdd(&cursor[d], 1);
        csrsrc[pos] = src[i];
    }
}

// ---------------- GEMM: H[M,96] = X[M,K] @ W[K,96] ----------------
// BM=64, BN=96, BK=32, 256 threads, thread tile 4x6
__global__ __launch_bounds__(256) void gemm_kernel(const float* __restrict__ X,
                                                   const float* __restrict__ W,
                                                   float* __restrict__ H, int M, int K) {
    __shared__ float Xs[32][64];
    __shared__ float Ws[32][96];
    int tid = threadIdx.x;
    int m0 = blockIdx.x * 64;
    int tr = tid >> 4, tc = tid & 15;
    float acc[4][6];
#pragma unroll
    for (int i = 0; i < 4; i++)
#pragma unroll
        for (int j = 0; j < 6; j++) acc[i][j] = 0.f;

    for (int k0 = 0; k0 < K; k0 += 32) {
        // X tile: 64 rows x 32 k = 512 float4, 2 per thread (transposed store)
#pragma unroll
        for (int q = 0; q < 2; q++) {
            int f = tid * 2 + q;
            int r = f >> 3;
            int kk = (f & 7) << 2;
            float4 v = make_float4(0.f, 0.f, 0.f, 0.f);
            int gm = m0 + r;
            if (gm < M) v = *(const float4*)&X[(size_t)gm * K + k0 + kk];
            Xs[kk][r] = v.x; Xs[kk + 1][r] = v.y; Xs[kk + 2][r] = v.z; Xs[kk + 3][r] = v.w;
        }
        // W tile: 32 rows x 96 cols = 768 float4, 3 per thread
#pragma unroll
        for (int q = 0; q < 3; q++) {
            int f = tid * 3 + q;
            int r = f / 24;
            int cc = (f % 24) * 4;
            float4 v = *(const float4*)&W[(size_t)(k0 + r) * 96 + cc];
            Ws[r][cc] = v.x; Ws[r][cc + 1] = v.y; Ws[r][cc + 2] = v.z; Ws[r][cc + 3] = v.w;
        }
        __syncthreads();
#pragma unroll
        for (int k = 0; k < 32; k++) {
            float a[4], b[6];
#pragma unroll
            for (int i = 0; i < 4; i++) a[i] = Xs[k][tr * 4 + i];
#pragma unroll
            for (int j = 0; j < 6; j++) b[j] = Ws[k][tc * 6 + j];
#pragma unroll
            for (int i = 0; i < 4; i++)
#pragma unroll
                for (int j = 0; j < 6; j++) acc[i][j] += a[i] * b[j];
        }
        __syncthreads();
    }
#pragma unroll
    for (int i = 0; i < 4; i++) {
        int gm = m0 + tr * 4 + i;
        if (gm < M) {
#pragma unroll
            for (int j = 0; j < 6; j++) H[(size_t)gm * 96 + tc * 6 + j] = acc[i][j];
        }
    }
}

// ---------------- attention coefficients: es/ed per (node, head) ----------------
template <int HEADS>
__global__ void attn_kernel(const float* __restrict__ Hb, const float* __restrict__ a_s,
                            const float* __restrict__ a_d, float* __restrict__ es,
                            float* __restrict__ ed, int n) {
    int w = (blockIdx.x * blockDim.x + threadIdx.x) >> 5;
    int lane = threadIdx.x & 31;
    if (w >= n) return;
    const float* hr = Hb + (size_t)w * 96;
    float s0 = 0, s1 = 0, d0 = 0, d1 = 0;
#pragma unroll
    for (int k = 0; k < 3; k++) {
        int ch = lane + 32 * k;
        float v = hr[ch];
        float as = a_s[ch], ad = a_d[ch];
        if (HEADS == 2 && ch >= 48) { s1 += v * as; d1 += v * ad; }
        else { s0 += v * as; d0 += v * ad; }
    }
#pragma unroll
    for (int off = 16; off; off >>= 1) {
        s0 += __shfl_xor_sync(~0u, s0, off);
        d0 += __shfl_xor_sync(~0u, d0, off);
        if (HEADS == 2) {
            s1 += __shfl_xor_sync(~0u, s1, off);
            d1 += __shfl_xor_sync(~0u, d1, off);
        }
    }
    if (lane == 0) {
        es[w * HEADS] = s0; ed[w * HEADS] = d0;
        if (HEADS == 2) { es[w * HEADS + 1] = s1; ed[w * HEADS + 1] = d1; }
    }
}

// ---------------- aggregation: warp per dst node, CSR gather ----------------
// softmax without max subtraction (algebraically identical; logits are O(5) here
// since weights are scaled by 0.1, so exp() stays well inside fp32 range)
template <int HEADS>
__global__ void agg_kernel(const float* __restrict__ Hb, const float* __restrict__ es,
                           const float* __restrict__ ed, const float* __restrict__ bias,
                           const int* __restrict__ row, const int* __restrict__ csrsrc,
                           float* __restrict__ Out, int n) {
    int w = (blockIdx.x * blockDim.x + threadIdx.x) >> 5;
    int lane = threadIdx.x & 31;
    if (w >= n) return;
    int beg = row[w], end = row[w + 1];
    float ed0, ed1 = 0;
    if (HEADS == 2) { float2 v = ((const float2*)ed)[w]; ed0 = v.x; ed1 = v.y; }
    else ed0 = ed[w];
    int c0 = lane, c1 = lane + 32, c2 = lane + 64;
    bool b1h = (HEADS == 2) && (c1 >= 48);   // mixed region head
    float acc0 = 0, acc1 = 0, acc2 = 0, s0 = 0, s1 = 0;
    for (int j = beg; j < end; j++) {
        int s = csrsrc[j];
        float p0, p1;
        if (HEADS == 2) {
            float2 ev = ((const float2*)es)[s];
            float e0 = ev.x + ed0; e0 = (e0 > 0.f) ? e0 : NEG_SLOPE * e0;
            float e1 = ev.y + ed1; e1 = (e1 > 0.f) ? e1 : NEG_SLOPE * e1;
            p0 = __expf(e0); p1 = __expf(e1);
        } else {
            float e0 = es[s] + ed0; e0 = (e0 > 0.f) ? e0 : NEG_SLOPE * e0;
            p0 = __expf(e0); p1 = p0;
        }
        s0 += p0; s1 += p1;
        const float* hr = Hb + (size_t)s * 96;
        float pb = b1h ? p1 : p0;
        float pc = (HEADS == 2) ? p1 : p0;
        acc0 += p0 * hr[c0];
        acc1 += pb * hr[c1];
        acc2 += pc * hr[c2];
    }
    float i0 = 1.f / s0, i1 = 1.f / s1;
    float ib = b1h ? i1 : i0;
    float ic = (HEADS == 2) ? i1 : i0;
    float o0 = acc0 * i0 + bias[c0];
    float o1 = acc1 * ib + bias[c1];
    float o2 = acc2 * ic + bias[c2];
    float* orow = Out + (size_t)w * 96;
    orow[c0] = fmaxf(o0, 0.f);
    orow[c1] = fmaxf(o1, 0.f);
    orow[c2] = fmaxf(o2, 0.f);
}

// ---------------- pooling + classifier ----------------
__global__ void zero_pool_kernel(float* gsum, float* gcnt) {
    int i = blockIdx.x * blockDim.x + threadIdx.x;
    if (i < N_GRAPHS * HH) gsum[i] = 0.f;
    if (i < N_GRAPHS) gcnt[i] = 0.f;
}

__global__ void pool_kernel(const float* __restrict__ X, const int* __restrict__ batch,
                            float* __restrict__ gsum, float* __restrict__ gcnt, int n) {
    int w = (blockIdx.x * blockDim.x + threadIdx.x) >> 5;
    int lane = threadIdx.x & 31;
    if (w >= n) return;
    int g = batch[w];
    const float* xr = X + (size_t)w * 96;
#pragma unroll
    for (int k = 0; k < 3; k++) {
        int ch = lane + 32 * k;
        atomicAdd(&gsum[g * 96 + ch], xr[ch]);
    }
    if (lane == 0) atomicAdd(&gcnt[g], 1.f);
}

__global__ void cls_kernel(const float* __restrict__ gsum, const float* __restrict__ gcnt,
                           const float* __restrict__ Wc, const float* __restrict__ bc,
                           float* __restrict__ out) {
    int g = blockIdx.x * blockDim.x + threadIdx.x;
    if (g >= N_GRAPHS) return;
    float cnt = fmaxf(gcnt[g], 1.f);
    float acc = 0.f;
    for (int c = 0; c < HH; c++) acc += gsum[g * 96 + c] * Wc[c];
    float z = acc / cnt + bc[0];
    out[g] = 1.f / (1.f + __expf(-z));
}

// ---------------- launch ----------------
extern "C" void kernel_launch(void* const* d_in, const int* in_sizes, int n_in,
                              void* d_out, int out_size) {
    const float* x      = (const float*)d_in[0];
    const void*  ei     = d_in[1];             // int32 or int64, probed at runtime
    // d_in[2] edge_weight: ignored (faithful to GATConv with edge_dim=None)
    const void*  batch  = d_in[3];
    const float* W[4]  = { (const float*)d_in[4],  (const float*)d_in[8],
                           (const float*)d_in[12], (const float*)d_in[16] };
    const float* As[4] = { (const float*)d_in[5],  (const float*)d_in[9],
                           (const float*)d_in[13], (const float*)d_in[17] };
    const float* Ad[4] = { (const float*)d_in[6],  (const float*)d_in[10],
                           (const float*)d_in[14], (const float*)d_in[18] };
    const float* B[4]  = { (const float*)d_in[7],  (const float*)d_in[11],
                           (const float*)d_in[15], (const float*)d_in[19] };
    const float* Wc = (const float*)d_in[20];
    const float* bc = (const float*)d_in[21];
    float* out = (float*)d_out;

    const int n = in_sizes[3];      // batch count = N
    const int e = in_sizes[2];      // edge_weight count = E

    int *p_flag, *p_src, *p_dst, *p_batch, *p_counts, *p_row, *p_cursor, *p_csrsrc;
    float *p_h, *p_A, *p_B, *p_es, *p_ed, *p_gsum, *p_gcnt;
    cudaGetSymbolAddress((void**)&p_flag,   g_flag64);
    cudaGetSymbolAddress((void**)&p_src,    g_src32);
    cudaGetSymbolAddress((void**)&p_dst,    g_dst32);
    cudaGetSymbolAddress((void**)&p_batch,  g_batch32);
    cudaGetSymbolAddress((void**)&p_counts, g_counts);
    cudaGetSymbolAddress((void**)&p_row,    g_row);
    cudaGetSymbolAddress((void**)&p_cursor, g_cursor);
    cudaGetSymbolAddress((void**)&p_csrsrc, g_csrsrc);
    cudaGetSymbolAddress((void**)&p_h,      g_h);
    cudaGetSymbolAddress((void**)&p_A,      g_bufA);
    cudaGetSymbolAddress((void**)&p_B,      g_bufB);
    cudaGetSymbolAddress((void**)&p_es,     g_es);
    cudaGetSymbolAddress((void**)&p_ed,     g_ed);
    cudaGetSymbolAddress((void**)&p_gsum,   g_gsum);
    cudaGetSymbolAddress((void**)&p_gcnt,   g_gcnt);

    // ---- probe index dtype, convert all indices to int32 ----
    probe_kernel<<<1, 1>>>((const int*)ei, p_flag);
    cvt_kernel<<<(e + 255) / 256, 256>>>(ei, 0,            p_flag, p_src,   e);
    cvt_kernel<<<(e + 255) / 256, 256>>>(ei, (long long)e, p_flag, p_dst,   e);
    cvt_kernel<<<(n + 255) / 256, 256>>>(batch, 0,         p_flag, p_batch, n);

    // ---- CSR build ----
    init_counts_kernel<<<(n + 255) / 256, 256>>>(p_counts, n);
    hist_kernel<<<(e + 255) / 256, 256>>>(p_dst, p_counts, e);
    scan_kernel<<<1, 1024>>>(p_counts, p_row, n);
    selfloop_kernel<<<(n + 255) / 256, 256>>>(p_row, p_cursor, p_csrsrc, n);
    scatter_kernel<<<(e + 255) / 256, 256>>>(p_src, p_dst, p_cursor, p_csrsrc, e);

    const int gemm_grid = (n + 63) / 64;
    const int warp_grid = (n * 32 + 255) / 256;   // warp-per-node kernels, 256 thr/block

    // ---- layer 1 (HEADS=2, K=128) ----
    gemm_kernel<<<gemm_grid, 256>>>(x, W[0], p_h, n, IN_CH);
    attn_kernel<2><<<warp_grid, 256>>>(p_h, As[0], Ad[0], p_es, p_ed, n);
    agg_kernel<2><<<warp_grid, 256>>>(p_h, p_es, p_ed, B[0], p_row, p_csrsrc, p_A, n);

    // ---- layers 2-4 (HEADS=1, K=96) ----
    float* bufs[2] = { p_A, p_B };
    for (int l = 1; l < 4; l++) {
        const float* in  = bufs[(l + 1) & 1];
        float*       ob  = bufs[l & 1];
        gemm_kernel<<<gemm_grid, 256>>>(in, W[l], p_h, n, HH);
        attn_kernel<1><<<warp_grid, 256>>>(p_h, As[l], Ad[l], p_es, p_ed, n);
        agg_kernel<1><<<warp_grid, 256>>>(p_h, p_es, p_ed, B[l], p_row, p_csrsrc, ob, n);
    }
    float* final_act = bufs[3 & 1];  // layer 4 output -> p_B

    // ---- pool + classify ----
    zero_pool_kernel<<<(N_GRAPHS * HH + 255) / 256, 256>>>(p_gsum, p_gcnt);
    pool_kernel<<<warp_grid, 256>>>(final_act, p_batch, p_gsum, p_gcnt, n);
    cls_kernel<<<1, 64>>>(p_gsum, p_gcnt, Wc, bc, out);
}